// round 4
// baseline (speedup 1.0000x reference)
#include <cuda_runtime.h>
#include <math_constants.h>

#define SIZE 28
#define TSTEPS 64
#define PITCH 32        // t-row pitch in floats (px) / float2s (pywp)
#define NTHREADS 224    // 7 warps; 196 active in mainloop; 1792/224 = 8 prologue iters

__global__ __launch_bounds__(NTHREADS, 6) void draw_image_kernel(
    const float* __restrict__ x,   // (B, T, 3)
    float* __restrict__ out)       // (B, SIZE, SIZE)
{
    __shared__ float  s_px  [TSTEPS * PITCH];  // log-domain: -g*(rng[c]-x_t)^2
    __shared__ float2 s_pywp[TSTEPS * PITCH];  // duplicated (w,w), w = log(si)-g*(rng[r]-y_t)^2
    __shared__ float  s_x   [TSTEPS * 3];      // staged stroke params
    __shared__ float  s_ls  [TSTEPS];          // log(si_t)

    const int b = blockIdx.x;
    const int tid = threadIdx.x;
    const float* xb = x + (size_t)b * TSTEPS * 3;

    const float g = (SIZE * 0.5f) * (SIZE * 0.5f);  // 196
    const float inv_size = 1.0f / SIZE;

    // Phase 0 (concurrent): stage params (threads 0..47) and compute the 64
    // logs straight from global (threads 64..127). Independent -> one barrier.
    if (tid < 48) {
        ((float4*)s_x)[tid] = ((const float4*)xb)[tid];
    } else if (tid >= 64 && tid < 128) {
        const int t = tid - 64;
        s_ls[t] = __logf(xb[3 * t + 2]);
    }
    __syncthreads();

    // Phase 1: log-domain tables. pyw stored duplicated for packed-f32x2 use.
    #pragma unroll
    for (int it = 0; it < 8; it++) {
        const int i = tid + it * NTHREADS;
        const int t = i / SIZE;
        const int c = i - t * SIZE;
        const float rng = (float)c * inv_size - 0.5f;

        const float sx = s_x[3 * t + 0];
        const float sy = s_x[3 * t + 1];

        const float dx = rng - sx;
        s_px[t * PITCH + c] = (dx * dx) * (-g);

        const float dy = rng - sy;
        const float w = fmaf(dy * dy, -g, s_ls[t]);
        s_pywp[t * PITCH + c] = make_float2(w, w);   // STS.64
    }
    __syncthreads();

    // Mainloop: 196 units = (cg in [0,7)) x (r in [0,28)), 4 px per thread.
    // Per t: LDS.64 (w,w) + LDS.128 (p0..p3) + 2x add.f32x2 + 4x FMNMX.
    if (tid < 196) {
        const int cg = tid / SIZE;        // 0..6
        const int r  = tid - cg * SIZE;   // 0..27

        const float4* px4 = (const float4*)s_px;
        const unsigned long long* pywp =
            (const unsigned long long*)s_pywp;      // [t * PITCH + r]

        const float ninf = -CUDART_INF_F;
        float a0 = ninf, a1 = ninf, a2 = ninf, a3 = ninf;

        #pragma unroll
        for (int t = 0; t < TSTEPS; t++) {
            const unsigned long long wp = pywp[t * PITCH + r];   // LDS.64
            const float4 p = px4[t * (PITCH / 4) + cg];          // LDS.128

            unsigned long long p01, p23, s01, s23;
            asm("mov.b64 %0, {%1, %2};" : "=l"(p01) : "f"(p.x), "f"(p.y));
            asm("mov.b64 %0, {%1, %2};" : "=l"(p23) : "f"(p.z), "f"(p.w));
            asm("add.rn.f32x2 %0, %1, %2;" : "=l"(s01) : "l"(p01), "l"(wp));
            asm("add.rn.f32x2 %0, %1, %2;" : "=l"(s23) : "l"(p23), "l"(wp));

            float s0, s1, s2, s3;
            asm("mov.b64 {%0, %1}, %2;" : "=f"(s0), "=f"(s1) : "l"(s01));
            asm("mov.b64 {%0, %1}, %2;" : "=f"(s2), "=f"(s3) : "l"(s23));

            a0 = fmaxf(a0, s0);
            a1 = fmaxf(a1, s1);
            a2 = fmaxf(a2, s2);
            a3 = fmaxf(a3, s3);
        }

        // Leave log domain: 4 exps per thread, one STG.128.
        float* outp = out + (size_t)b * SIZE * SIZE + r * SIZE + cg * 4;
        *(float4*)outp = make_float4(__expf(a0), __expf(a1), __expf(a2), __expf(a3));
    }
}

extern "C" void kernel_launch(void* const* d_in, const int* in_sizes, int n_in,
                              void* d_out, int out_size)
{
    const float* x = (const float*)d_in[0];
    float* out = (float*)d_out;

    const int B = in_sizes[0] / (TSTEPS * 3);  // 1024

    draw_image_kernel<<<B, NTHREADS>>>(x, out);
}

// round 5
// speedup vs baseline: 1.2792x; 1.2792x over previous
#include <cuda_runtime.h>
#include <math_constants.h>

#define SIZE 28
#define TSTEPS 64
#define PITCH 32        // float2 entries per t-row in the uq table
#define NTHREADS 224    // 7 warps; 196 active in mainloop; 1792/224 = 8 prologue iters

__global__ __launch_bounds__(NTHREADS) void draw_image_kernel(
    const float* __restrict__ x,   // (B, T, 3)
    float* __restrict__ out)       // (B, SIZE, SIZE)
{
    // uq[t][r] = (u_t, q_{t,r}) with
    //   u_t    = 2*g*x_t
    //   q_{t,r}= log(si_t) - g*(rng_r - y_t)^2 - g*x_t^2
    // pixel value (log domain): s = q + u*rng_c + e_c,  e_c = -g*rng_c^2 (const in t)
    __shared__ float2 s_uq[TSTEPS * PITCH];   // 16 KB
    __shared__ float  s_x [TSTEPS * 3];       // staged stroke params
    __shared__ float  s_ls[TSTEPS];           // log(si_t)

    const int b = blockIdx.x;
    const int tid = threadIdx.x;
    const float* xb = x + (size_t)b * TSTEPS * 3;

    const float g = (SIZE * 0.5f) * (SIZE * 0.5f);  // 196
    const float inv_size = 1.0f / SIZE;

    // Phase 0 (concurrent): stage params (threads 0..47); logs (threads 64..127).
    if (tid < 48) {
        ((float4*)s_x)[tid] = ((const float4*)xb)[tid];
    } else if (tid >= 64 && tid < 128) {
        const int t = tid - 64;
        s_ls[t] = __logf(xb[3 * t + 2]);
    }
    __syncthreads();

    // Phase 1: build uq table. Fixed r per thread; t strides by 8.
    {
        const int t0 = tid / SIZE;            // 0..7
        const int r  = tid - t0 * SIZE;       // 0..27
        const float rng_r = (float)r * inv_size - 0.5f;

        #pragma unroll
        for (int it = 0; it < 8; it++) {
            const int t = t0 + it * 8;
            const float sx = s_x[3 * t + 0];
            const float sy = s_x[3 * t + 1];
            const float ls = s_ls[t];

            const float u  = (2.0f * g) * sx;
            const float dy = rng_r - sy;
            const float w  = fmaf(dy * dy, -g, ls);       // ls - g*dy^2
            const float q  = fmaf(sx * sx, -g, w);        // w  - g*x^2

            s_uq[t * PITCH + r] = make_float2(u, q);      // STS.64
        }
    }
    __syncthreads();

    // Mainloop: 196 units = (cg in [0,7)) x (r in [0,28)), 4 px per thread.
    // Per t: one LDS.64 + 4 FFMA + 4 FMNMX.
    if (tid < 196) {
        const int cg = tid / SIZE;        // 0..6
        const int r  = tid - cg * SIZE;   // 0..27

        const float rc0 = (float)(cg * 4 + 0) * inv_size - 0.5f;
        const float rc1 = (float)(cg * 4 + 1) * inv_size - 0.5f;
        const float rc2 = (float)(cg * 4 + 2) * inv_size - 0.5f;
        const float rc3 = (float)(cg * 4 + 3) * inv_size - 0.5f;

        const float ninf = -CUDART_INF_F;
        float a0 = ninf, a1 = ninf, a2 = ninf, a3 = ninf;

        #pragma unroll
        for (int t = 0; t < TSTEPS; t++) {
            const float2 uq = s_uq[t * PITCH + r];        // LDS.64, conflict-free
            a0 = fmaxf(a0, fmaf(uq.x, rc0, uq.y));
            a1 = fmaxf(a1, fmaf(uq.x, rc1, uq.y));
            a2 = fmaxf(a2, fmaf(uq.x, rc2, uq.y));
            a3 = fmaxf(a3, fmaf(uq.x, rc3, uq.y));
        }

        // Add the hoisted e_c = -g*rng_c^2 and leave log domain.
        const float e0 = -g * rc0 * rc0;
        const float e1 = -g * rc1 * rc1;
        const float e2 = -g * rc2 * rc2;
        const float e3 = -g * rc3 * rc3;

        float* outp = out + (size_t)b * SIZE * SIZE + r * SIZE + cg * 4;
        *(float4*)outp = make_float4(__expf(a0 + e0), __expf(a1 + e1),
                                     __expf(a2 + e2), __expf(a3 + e3));
    }
}

extern "C" void kernel_launch(void* const* d_in, const int* in_sizes, int n_in,
                              void* d_out, int out_size)
{
    const float* x = (const float*)d_in[0];
    float* out = (float*)d_out;

    const int B = in_sizes[0] / (TSTEPS * 3);  // 1024

    draw_image_kernel<<<B, NTHREADS>>>(x, out);
}

// round 6
// speedup vs baseline: 1.3167x; 1.0293x over previous
#include <cuda_runtime.h>
#include <math_constants.h>

#define SIZE 28
#define TSTEPS 64
#define NPAIR (TSTEPS / 2)   // 32 t-pairs
#define NTHREADS 224         // 7 warps; 196 active in mainloop

__global__ __launch_bounds__(NTHREADS, 5) void draw_image_kernel(
    const float* __restrict__ x,   // (B, T, 3)
    float* __restrict__ out)       // (B, SIZE, SIZE)
{
    // uq[t2][r] = (u_{2t2}, q_{2t2,r}, u_{2t2+1}, q_{2t2+1,r})
    //   u_t     = 2*g*x_t
    //   q_{t,r} = log(si_t) - g*(rng_r - y_t)^2 - g*x_t^2
    // pixel (log domain): s = q + u*rng_c + e_c,  e_c = -g*rng_c^2
    __shared__ float4 s_uq[NPAIR * SIZE];   // 32*28*16 = 14336 B
    __shared__ float  s_x [TSTEPS * 3];
    __shared__ float  s_ls[TSTEPS];

    const int b = blockIdx.x;
    const int tid = threadIdx.x;
    const float* xb = x + (size_t)b * TSTEPS * 3;

    const float g = (SIZE * 0.5f) * (SIZE * 0.5f);  // 196
    const float inv_size = 1.0f / SIZE;

    // Phase 0 (concurrent): stage params (threads 0..47); logs (threads 64..127).
    if (tid < 48) {
        ((float4*)s_x)[tid] = ((const float4*)xb)[tid];
    } else if (tid >= 64 && tid < 128) {
        const int t = tid - 64;
        s_ls[t] = __logf(xb[3 * t + 2]);
    }
    __syncthreads();

    // Phase 1: build paired table. Fixed r per thread; t2 strides by 8 (4 iters).
    {
        const int p0 = tid / SIZE;            // 0..7
        const int r  = tid - p0 * SIZE;       // 0..27
        const float rng_r = (float)r * inv_size - 0.5f;

        #pragma unroll
        for (int it = 0; it < 4; it++) {
            const int t2 = p0 + it * 8;       // 0..31
            const int ta = 2 * t2;
            const int tb = ta + 1;

            const float xa = s_x[3 * ta + 0], ya = s_x[3 * ta + 1];
            const float xbp = s_x[3 * tb + 0], yb = s_x[3 * tb + 1];

            const float ua = (2.0f * g) * xa;
            const float ub = (2.0f * g) * xbp;

            const float dya = rng_r - ya;
            const float qa = fmaf(xa * xa, -g, fmaf(dya * dya, -g, s_ls[ta]));
            const float dyb = rng_r - yb;
            const float qb = fmaf(xbp * xbp, -g, fmaf(dyb * dyb, -g, s_ls[tb]));

            s_uq[t2 * SIZE + r] = make_float4(ua, qa, ub, qb);   // STS.128
        }
    }
    __syncthreads();

    // Mainloop: 196 units = (cg in [0,7)) x (r in [0,28)), 4 px per thread.
    // Per t-pair: one LDS.128 + 8 FFMA + 8 FMNMX.
    if (tid < 196) {
        const int cg = tid / SIZE;        // 0..6
        const int r  = tid - cg * SIZE;   // 0..27

        const float rc0 = (float)(cg * 4 + 0) * inv_size - 0.5f;
        const float rc1 = (float)(cg * 4 + 1) * inv_size - 0.5f;
        const float rc2 = (float)(cg * 4 + 2) * inv_size - 0.5f;
        const float rc3 = (float)(cg * 4 + 3) * inv_size - 0.5f;

        const float ninf = -CUDART_INF_F;
        float a0 = ninf, a1 = ninf, a2 = ninf, a3 = ninf;

        const float4* uq = s_uq + r;      // stride SIZE per t-pair

        #pragma unroll
        for (int t2 = 0; t2 < NPAIR; t2++) {
            const float4 p = uq[t2 * SIZE];               // LDS.128
            a0 = fmaxf(a0, fmaf(p.x, rc0, p.y));
            a1 = fmaxf(a1, fmaf(p.x, rc1, p.y));
            a2 = fmaxf(a2, fmaf(p.x, rc2, p.y));
            a3 = fmaxf(a3, fmaf(p.x, rc3, p.y));
            a0 = fmaxf(a0, fmaf(p.z, rc0, p.w));
            a1 = fmaxf(a1, fmaf(p.z, rc1, p.w));
            a2 = fmaxf(a2, fmaf(p.z, rc2, p.w));
            a3 = fmaxf(a3, fmaf(p.z, rc3, p.w));
        }

        // Hoisted e_c = -g*rng_c^2, then leave log domain.
        const float e0 = -g * rc0 * rc0;
        const float e1 = -g * rc1 * rc1;
        const float e2 = -g * rc2 * rc2;
        const float e3 = -g * rc3 * rc3;

        float* outp = out + (size_t)b * SIZE * SIZE + r * SIZE + cg * 4;
        *(float4*)outp = make_float4(__expf(a0 + e0), __expf(a1 + e1),
                                     __expf(a2 + e2), __expf(a3 + e3));
    }
}

extern "C" void kernel_launch(void* const* d_in, const int* in_sizes, int n_in,
                              void* d_out, int out_size)
{
    const float* x = (const float*)d_in[0];
    float* out = (float*)d_out;

    const int B = in_sizes[0] / (TSTEPS * 3);  // 1024

    draw_image_kernel<<<B, NTHREADS>>>(x, out);
}

// round 7
// speedup vs baseline: 1.3206x; 1.0029x over previous
#include <cuda_runtime.h>
#include <math_constants.h>

#define SIZE 28
#define TSTEPS 64
#define TPITCH 32            // float2 entries per t-row (r-pitch, padded 28->32)
#define NTHREADS 224         // 7 warps; warp w owns column group w
#define CULL_R 0.3036f       // 1.5/28 (window halfwidth) + 0.25 (e^-12.25 tail)

__global__ __launch_bounds__(NTHREADS, 7) void draw_image_kernel(
    const float* __restrict__ x,   // (B, T, 3)
    float* __restrict__ out)       // (B, SIZE, SIZE)
{
    // uq[t][r] = (u_t, q_{t,r}),  u_t = 2*g*x_t,
    // q = log(si_t) - g*(rng_r - y_t)^2 - g*x_t^2
    // pixel (log): s = q + u*rng_c + e_c,  e_c = -g*rng_c^2
    __shared__ float2   s_uq  [TSTEPS * TPITCH];  // 16 KB
    __shared__ float    s_x   [TSTEPS * 3];
    __shared__ float    s_ls  [TSTEPS];
    __shared__ unsigned s_list[7 * TSTEPS];       // premultiplied byte offsets (t<<8)

    const int b    = blockIdx.x;
    const int tid  = threadIdx.x;
    const int wid  = tid >> 5;
    const int lane = tid & 31;
    const float* xb = x + (size_t)b * TSTEPS * 3;

    const float g = 196.0f;                  // (SIZE/2)^2
    const float inv_size = 1.0f / SIZE;

    // Phase 0 (concurrent): stage params; 64 logs.
    if (tid < 48) {
        ((float4*)s_x)[tid] = ((const float4*)xb)[tid];
    } else if (tid >= 64 && tid < 128) {
        const int t = tid - 64;
        s_ls[t] = __logf(xb[3 * t + 2]);
    }
    __syncthreads();

    // Phase 1a: per-warp survivor list for column group cg = wid.
    // Keep stroke t iff |x_t - window_mid| < CULL_R. Dropped strokes
    // contribute < e^-12 absolute; max over a subset is always <= ref.
    const float mid = ((float)(wid * 4) + 1.5f) * inv_size - 0.5f;
    int cnt = 0;
    #pragma unroll
    for (int h = 0; h < 2; h++) {
        const int t = lane + 32 * h;
        const float xt = s_x[3 * t];
        const bool keep = fabsf(xt - mid) < CULL_R;
        const unsigned m = __ballot_sync(0xffffffffu, keep);
        if (keep) {
            const int pos = cnt + __popc(m & ((1u << lane) - 1u));
            s_list[wid * TSTEPS + pos] = (unsigned)(t << 8);  // t * TPITCH * 8
        }
        cnt += __popc(m);
    }
    const int n4 = (cnt + 3) & ~3;                 // pad to multiple of 4
    if (lane < n4 - cnt) s_list[wid * TSTEPS + cnt + lane] = 0;  // dup t=0: harmless

    // Phase 1b: build uq table (all 224 threads; fixed r, t strides by 8).
    {
        const int t0 = tid / SIZE;            // 0..7
        const int r  = tid - t0 * SIZE;       // 0..27
        const float rng_r = (float)r * inv_size - 0.5f;
        #pragma unroll
        for (int it = 0; it < 8; it++) {
            const int t = t0 + it * 8;
            const float sx = s_x[3 * t];
            const float sy = s_x[3 * t + 1];
            const float u  = (2.0f * g) * sx;
            const float dy = rng_r - sy;
            const float q  = fmaf(sx * sx, -g, fmaf(dy * dy, -g, s_ls[t]));
            s_uq[t * TPITCH + r] = make_float2(u, q);          // STS.64
        }
    }
    __syncthreads();   // table visible (own-warp list needs no barrier, covered anyway)

    // Mainloop: warp w = column group w; lane = row r (lanes 28-31 compute
    // into padded table rows and discard). Per listed stroke:
    // IADD + LDS.64 + 4 FFMA + 4 FMNMX; offsets fetched 4-at-a-time (LDS.128).
    const int r = lane;
    const float rc0 = (float)(wid * 4 + 0) * inv_size - 0.5f;
    const float rc1 = (float)(wid * 4 + 1) * inv_size - 0.5f;
    const float rc2 = (float)(wid * 4 + 2) * inv_size - 0.5f;
    const float rc3 = (float)(wid * 4 + 3) * inv_size - 0.5f;

    const char* uqb = (const char*)s_uq + r * 8;
    const unsigned* lst = s_list + wid * TSTEPS;

    const float ninf = -CUDART_INF_F;
    float a0 = ninf, a1 = ninf, a2 = ninf, a3 = ninf;

    for (int i = 0; i < n4; i += 4) {
        const uint4 off = *(const uint4*)(lst + i);   // uniform LDS.128 broadcast

        const float2 p0 = *(const float2*)(uqb + off.x);
        a0 = fmaxf(a0, fmaf(p0.x, rc0, p0.y));
        a1 = fmaxf(a1, fmaf(p0.x, rc1, p0.y));
        a2 = fmaxf(a2, fmaf(p0.x, rc2, p0.y));
        a3 = fmaxf(a3, fmaf(p0.x, rc3, p0.y));

        const float2 p1 = *(const float2*)(uqb + off.y);
        a0 = fmaxf(a0, fmaf(p1.x, rc0, p1.y));
        a1 = fmaxf(a1, fmaf(p1.x, rc1, p1.y));
        a2 = fmaxf(a2, fmaf(p1.x, rc2, p1.y));
        a3 = fmaxf(a3, fmaf(p1.x, rc3, p1.y));

        const float2 p2 = *(const float2*)(uqb + off.z);
        a0 = fmaxf(a0, fmaf(p2.x, rc0, p2.y));
        a1 = fmaxf(a1, fmaf(p2.x, rc1, p2.y));
        a2 = fmaxf(a2, fmaf(p2.x, rc2, p2.y));
        a3 = fmaxf(a3, fmaf(p2.x, rc3, p2.y));

        const float2 p3 = *(const float2*)(uqb + off.w);
        a0 = fmaxf(a0, fmaf(p3.x, rc0, p3.y));
        a1 = fmaxf(a1, fmaf(p3.x, rc1, p3.y));
        a2 = fmaxf(a2, fmaf(p3.x, rc2, p3.y));
        a3 = fmaxf(a3, fmaf(p3.x, rc3, p3.y));
    }

    // Epilogue: hoisted e_c, leave log domain, one STG.128 per active lane.
    if (lane < SIZE) {
        const float e0 = -g * rc0 * rc0;
        const float e1 = -g * rc1 * rc1;
        const float e2 = -g * rc2 * rc2;
        const float e3 = -g * rc3 * rc3;
        float* outp = out + (size_t)b * SIZE * SIZE + r * SIZE + wid * 4;
        *(float4*)outp = make_float4(__expf(a0 + e0), __expf(a1 + e1),
                                     __expf(a2 + e2), __expf(a3 + e3));
    }
}

extern "C" void kernel_launch(void* const* d_in, const int* in_sizes, int n_in,
                              void* d_out, int out_size)
{
    const float* x = (const float*)d_in[0];
    float* out = (float*)d_out;

    const int B = in_sizes[0] / (TSTEPS * 3);  // 1024

    draw_image_kernel<<<B, NTHREADS>>>(x, out);
}

// round 8
// speedup vs baseline: 1.5645x; 1.1847x over previous
#include <cuda_runtime.h>
#include <math_constants.h>

#define SIZE 28
#define TSTEPS 64
#define NTHREADS 224         // 7 warps; warp w owns column group w (4 cols x 28 rows)
#define CULL_R 0.29f         // 1.5/28 window halfwidth + 0.2364 tail (abs err < 2e-5)

__global__ __launch_bounds__(NTHREADS) void draw_image_kernel(
    const float* __restrict__ x,   // (B, T, 3)
    float* __restrict__ out)       // (B, SIZE, SIZE)
{
    // Fully separable log2-domain form:
    //   s(t, r, c) = w_t + v_t*rr + u_t*rc + e_r + e_c
    //   u = 2*G2*x_t, v = 2*G2*y_t, w = log2(si_t) - G2*(x^2 + y^2)
    //   e_r = -G2*rr^2, e_c = -G2*rc^2  (hoisted out of the max)
    // out = exp2( max_t s )
    __shared__ float4 s_list[7 * TSTEPS];   // per-warp compacted (u, v, w, 0)
    __shared__ float  s_x   [TSTEPS * 3];
    __shared__ float  s_ls  [TSTEPS];       // log2(si_t)

    const int b    = blockIdx.x;
    const int tid  = threadIdx.x;
    const int wid  = tid >> 5;
    const int lane = tid & 31;
    const float* xb = x + (size_t)b * TSTEPS * 3;

    const float G2 = 196.0f * 1.4426950408889634f;  // (SIZE/2)^2 * log2(e)
    const float inv_size = 1.0f / SIZE;

    // Phase 0 (concurrent): stage params; 64 log2's.
    if (tid < 48) {
        ((float4*)s_x)[tid] = ((const float4*)xb)[tid];
    } else if (tid >= 64 && tid < 128) {
        const int t = tid - 64;
        s_ls[t] = __log2f(xb[3 * t + 2]);
    }
    __syncthreads();

    // Phase 1: per-warp survivor list with precomputed (u, v, w).
    // Keep stroke iff |x_t - window_mid| < CULL_R (dropped tail < 2e-5 abs;
    // max over a subset is always <= ref).
    const float mid = ((float)(wid * 4) + 1.5f) * inv_size - 0.5f;
    float4* lst = s_list + wid * TSTEPS;
    int cnt = 0;
    #pragma unroll
    for (int h = 0; h < 2; h++) {
        const int t = lane + 32 * h;
        const float xt = s_x[3 * t + 0];
        const bool keep = fabsf(xt - mid) < CULL_R;
        const unsigned m = __ballot_sync(0xffffffffu, keep);
        if (keep) {
            const float yt = s_x[3 * t + 1];
            const float u  = (2.0f * G2) * xt;
            const float v  = (2.0f * G2) * yt;
            const float w  = fmaf(fmaf(xt, xt, yt * yt), -G2, s_ls[t]);
            const int pos = cnt + __popc(m & ((1u << lane) - 1u));
            lst[pos] = make_float4(u, v, w, 0.0f);   // STS.128
        }
        cnt += __popc(m);
    }
    const int n4 = (cnt + 3) & ~3;
    if (lane < n4 - cnt)  // padding that can never win the max (0*finite - inf = -inf)
        lst[cnt + lane] = make_float4(0.0f, 0.0f, -CUDART_INF_F, 0.0f);
    __syncwarp();          // list is per-warp private: warp sync suffices

    // Mainloop: lane = row r, 4 px along columns. Per stroke:
    // one uniform LDS.128 broadcast + 1 FFMA (h) + 4 FFMA + 4 FMNMX.
    const int r = lane;
    const float rr  = (float)r * inv_size - 0.5f;
    const float rc0 = (float)(wid * 4 + 0) * inv_size - 0.5f;
    const float rc1 = (float)(wid * 4 + 1) * inv_size - 0.5f;
    const float rc2 = (float)(wid * 4 + 2) * inv_size - 0.5f;
    const float rc3 = (float)(wid * 4 + 3) * inv_size - 0.5f;

    const float ninf = -CUDART_INF_F;
    float a0 = ninf, a1 = ninf, a2 = ninf, a3 = ninf;

    for (int i = 0; i < n4; i += 4) {
        #pragma unroll
        for (int j = 0; j < 4; j++) {
            const float4 s = lst[i + j];               // LDS.128, imm offset, broadcast
            const float hh = fmaf(s.y, rr, s.z);       // v*rr + w
            a0 = fmaxf(a0, fmaf(s.x, rc0, hh));
            a1 = fmaxf(a1, fmaf(s.x, rc1, hh));
            a2 = fmaxf(a2, fmaf(s.x, rc2, hh));
            a3 = fmaxf(a3, fmaf(s.x, rc3, hh));
        }
    }

    // Epilogue: add hoisted e_r + e_c, leave log2 domain (raw EX2), STG.128.
    if (lane < SIZE) {
        const float er = -G2 * rr * rr;
        const float e0 = fmaf(-G2 * rc0, rc0, er);
        const float e1 = fmaf(-G2 * rc1, rc1, er);
        const float e2 = fmaf(-G2 * rc2, rc2, er);
        const float e3 = fmaf(-G2 * rc3, rc3, er);

        float o0, o1, o2, o3;
        asm("ex2.approx.ftz.f32 %0, %1;" : "=f"(o0) : "f"(a0 + e0));
        asm("ex2.approx.ftz.f32 %0, %1;" : "=f"(o1) : "f"(a1 + e1));
        asm("ex2.approx.ftz.f32 %0, %1;" : "=f"(o2) : "f"(a2 + e2));
        asm("ex2.approx.ftz.f32 %0, %1;" : "=f"(o3) : "f"(a3 + e3));

        float* outp = out + (size_t)b * SIZE * SIZE + r * SIZE + wid * 4;
        *(float4*)outp = make_float4(o0, o1, o2, o3);
    }
}

extern "C" void kernel_launch(void* const* d_in, const int* in_sizes, int n_in,
                              void* d_out, int out_size)
{
    const float* x = (const float*)d_in[0];
    float* out = (float*)d_out;

    const int B = in_sizes[0] / (TSTEPS * 3);  // 1024

    draw_image_kernel<<<B, NTHREADS>>>(x, out);
}

// round 9
// speedup vs baseline: 1.7539x; 1.1211x over previous
#include <cuda_runtime.h>
#include <math_constants.h>

#define SIZE 28
#define TSTEPS 64
#define NTHREADS 224         // 7 fully-autonomous warps; warp w owns columns 4w..4w+3
#define CULL_R 0.2736f       // 1.5/28 window halfwidth + 0.22 tail (drop < 7.5e-5 abs)

__global__ __launch_bounds__(NTHREADS) void draw_image_kernel(
    const float* __restrict__ x,   // (B, T, 3)
    float* __restrict__ out)       // (B, SIZE, SIZE)
{
    // Separable log2-domain form, u*rc0 pre-folded into w:
    //   s(t, r, ck) = w'_t + v_t*rr + u_t*(k/SIZE),  k = 0..3
    //   u = 2*G2*x_t, v = 2*G2*y_t,
    //   w' = log2(si_t) - G2*(x^2+y^2) + u*rc0
    //   hoisted per-pixel: e = -G2*(rr^2 + rc_k^2)
    // out = exp2( max_t s + e )
    __shared__ float4 s_list[7 * TSTEPS];   // per-warp private compacted lists

    const int b    = blockIdx.x;
    const int tid  = threadIdx.x;
    const int wid  = tid >> 5;
    const int lane = tid & 31;
    const float* xb = x + (size_t)b * TSTEPS * 3;

    const float G2 = 196.0f * 1.4426950408889634f;  // (SIZE/2)^2 * log2(e)
    const float inv_size = 1.0f / SIZE;

    const float rc0 = (float)(wid * 4) * inv_size - 0.5f;
    const float mid = rc0 + 1.5f * inv_size;        // center of the 4-col window

    // Phase 1 (per-warp, no CTA barrier anywhere): load params straight from
    // global (L1-shared across the CTA's warps), cull, compact into the
    // warp-private list. log2 computed only for survivors.
    float4* lst = s_list + wid * TSTEPS;
    int cnt = 0;
    #pragma unroll
    for (int h = 0; h < 2; h++) {
        const int t = lane + 32 * h;
        const float xt = __ldg(xb + 3 * t + 0);
        const float yt = __ldg(xb + 3 * t + 1);
        const float st = __ldg(xb + 3 * t + 2);

        const bool keep = fabsf(xt - mid) < CULL_R;
        const unsigned m = __ballot_sync(0xffffffffu, keep);
        if (keep) {
            const float ls = __log2f(st);
            const float u  = (2.0f * G2) * xt;
            const float v  = (2.0f * G2) * yt;
            float w = fmaf(fmaf(xt, xt, yt * yt), -G2, ls);
            w = fmaf(u, rc0, w);                   // fold u*rc0
            const int pos = cnt + __popc(m & ((1u << lane) - 1u));
            lst[pos] = make_float4(u, v, w, 0.0f); // STS.128
        }
        cnt += __popc(m);
    }
    const int n4 = (cnt + 3) & ~3;
    if (lane < n4 - cnt)   // padding can never win: fmaf(0, d, -inf) = -inf (no NaN)
        lst[cnt + lane] = make_float4(0.0f, 0.0f, -CUDART_INF_F, 0.0f);
    __syncwarp();

    // Phase 2: lane = row r; 4 px along columns. Per stroke:
    // 1/4 LDS.128 (uniform broadcast) + 4 FFMA + 4 FMNMX.
    const float rr = (float)lane * inv_size - 0.5f;
    const float d1 = 1.0f * inv_size;
    const float d2 = 2.0f * inv_size;
    const float d3 = 3.0f * inv_size;

    const float ninf = -CUDART_INF_F;
    float a0 = ninf, a1 = ninf, a2 = ninf, a3 = ninf;

    for (int i = 0; i < n4; i += 4) {
        #pragma unroll
        for (int j = 0; j < 4; j++) {
            const float4 s = lst[i + j];            // LDS.128, imm offset
            const float hh = fmaf(s.y, rr, s.z);    // v*rr + w'
            a0 = fmaxf(a0, hh);
            a1 = fmaxf(a1, fmaf(s.x, d1, hh));
            a2 = fmaxf(a2, fmaf(s.x, d2, hh));
            a3 = fmaxf(a3, fmaf(s.x, d3, hh));
        }
    }

    // Epilogue: hoisted e = -G2*(rr^2 + rc_k^2), raw EX2, one STG.128.
    if (lane < SIZE) {
        const float rc1 = rc0 + d1, rc2 = rc0 + d2, rc3 = rc0 + d3;
        const float er = -G2 * rr * rr;
        const float e0 = fmaf(-G2 * rc0, rc0, er);
        const float e1 = fmaf(-G2 * rc1, rc1, er);
        const float e2 = fmaf(-G2 * rc2, rc2, er);
        const float e3 = fmaf(-G2 * rc3, rc3, er);

        float o0, o1, o2, o3;
        asm("ex2.approx.ftz.f32 %0, %1;" : "=f"(o0) : "f"(a0 + e0));
        asm("ex2.approx.ftz.f32 %0, %1;" : "=f"(o1) : "f"(a1 + e1));
        asm("ex2.approx.ftz.f32 %0, %1;" : "=f"(o2) : "f"(a2 + e2));
        asm("ex2.approx.ftz.f32 %0, %1;" : "=f"(o3) : "f"(a3 + e3));

        float* outp = out + (size_t)b * SIZE * SIZE + lane * SIZE + wid * 4;
        *(float4*)outp = make_float4(o0, o1, o2, o3);
    }
}

extern "C" void kernel_launch(void* const* d_in, const int* in_sizes, int n_in,
                              void* d_out, int out_size)
{
    const float* x = (const float*)d_in[0];
    float* out = (float*)d_out;

    const int B = in_sizes[0] / (TSTEPS * 3);  // 1024

    draw_image_kernel<<<B, NTHREADS>>>(x, out);
}